// round 3
// baseline (speedup 1.0000x reference)
#include <cuda_runtime.h>

typedef unsigned long long u64;

#define OUT_H   32
#define OUT_W   256
#define IMG_H   256
#define IMG_W   512
#define NBLK    256
#define NGRP    66               // 8-e groups per lane: e in [8*jg, 8*jg+528)
#define D_SIZE  287
#define E_LEN   776              // e in [0, 776) per row (NGRP coverage max = 775)
#define E_ROW   784              // padded global K row (floats)
#define KROW    784              // SMEM padded pair-row size in u64 (392 16B units)
#define NUNIT   388              // real 16B units per pair-row (776 e / 2)
#define SMEM_K_U64   (16 * KROW)                      // 12544 u64 = 100352 B
#define SMEM_BYTES   (SMEM_K_U64 * 8 + 1024 * 4)      // + 4KB padded image row

__device__ float g_K[D_SIZE * E_ROW];                 // 900 KB global Toeplitz table
__device__ float g_part[NBLK * OUT_H * OUT_W];        // 8 MB partials

__device__ __forceinline__ u64 ffma2(u64 a, u64 b, u64 c) {
    u64 d; asm("fma.rn.f32x2 %0, %1, %2, %3;" : "=l"(d) : "l"(a), "l"(b), "l"(c));
    return d;
}
__device__ __forceinline__ u64 pack2(float v) {
    u64 r; asm("mov.b64 %0, {%1, %1};" : "=l"(r) : "f"(v)); return r;
}
__device__ __forceinline__ void unpack2(u64 v, float& lo, float& hi) {
    asm("mov.b64 {%0, %1}, %2;" : "=f"(lo), "=f"(hi) : "l"(v));
}
__device__ __forceinline__ float frcp(float x) {
    float r; asm("rcp.approx.f32 %0, %1;" : "=f"(r) : "f"(x)); return r;
}

// ---------------------------------------------------------------------------
// Kernel 1: global Toeplitz table, K[d][e] = 1/((d-255+p0)^2 + (e-511+p1)^2)
// (220K MUFU.RCP chip-wide; built ONCE, not per block)
// ---------------------------------------------------------------------------
__global__ void fill_k_kernel(const float* __restrict__ pos) {
    int d = blockIdx.x;
    float dx  = (float)(d - 255) + pos[0];
    float dx2 = dx * dx;
    for (int e = threadIdx.x; e < E_LEN; e += blockDim.x) {
        float dy = (float)(e - 511) + pos[1];
        g_K[d * E_ROW + e] = frcp(fmaf(dy, dy, dx2));
    }
}

// ---------------------------------------------------------------------------
// Kernel 2: one block per image row ii.
//   P[ii][i][j] = sum_{e=j}^{j+511} K(i-ii+255, e) * img[ii][j+511-e]
// SMEM K layout: 16 pair-rows (i pairs), d-paired float2 per cell, 16B units
// XOR-swizzled: phys_unit = u ^ ((u>>3)&3)  ->  conflict-free LDS.128.
// Inner loop: pure fma.rn.f32x2 (128 per lane per 8-e group).
// ---------------------------------------------------------------------------
__global__ void __launch_bounds__(256, 2)
conv_part_kernel(const float* __restrict__ img) {
    extern __shared__ char smem[];
    u64*   sK   = (u64*)smem;
    float* sKf  = (float*)smem;
    float* simg = (float*)(smem + SMEM_K_U64 * 8);    // 1024 floats, zero-padded

    const int ii  = blockIdx.x;
    const int tid = threadIdx.x;

    // ---- stage image row (real data at [256,768), zeros elsewhere) ----
    for (int x = tid; x < 1024; x += 256) {
        float v = 0.0f;
        if (x >= 256 && x < 768) v = img[ii * IMG_W + (x - 256)];
        simg[x] = v;
    }

    // ---- copy 32 K rows from global into paired+swizzled SMEM ----
    // unit u holds e = {2u, 2u+1}; floats: {K[g0][2u], K[g1][2u], K[g0][2u+1], K[g1][2u+1]}
    for (int p = 0; p < 16; p++) {
        const float* r0 = g_K + (2 * p + 255 - ii) * E_ROW;      // dd = 2p
        const float* r1 = r0 + E_ROW;                            // dd = 2p+1
        float* dstp = sKf + p * (KROW * 2);
        for (int u = tid; u < NUNIT; u += 256) {
            float2 a = *(const float2*)(r0 + 2 * u);
            float2 b = *(const float2*)(r1 + 2 * u);
            int phys = u ^ ((u >> 3) & 3);
            *(float4*)(dstp + phys * 4) = make_float4(a.x, b.x, a.y, b.y);
        }
    }
    __syncthreads();

    // ---- main loop ----
    const int jg = tid & 31;           // j block: j = 8*jg + jj
    const int ig = tid >> 5;           // i block: i = 4*ig + r
    const u64* krow0 = sK + (2 * ig) * KROW;
    const u64* krow1 = krow0 + KROW;

    u64 acc0[8], acc1[8];
#pragma unroll
    for (int jj = 0; jj < 8; jj++) { acc0[jj] = 0ull; acc1[jj] = 0ull; }

    // broadcast image window: wp[k] = (v,v), v = simg[760 - 8*Gl + k]
    u64 wp[16];
    {
        const float4* p = (const float4*)(simg + 760);
        float4 a = p[0], b = p[1], c = p[2], d = p[3];
        wp[0]  = pack2(a.x); wp[1]  = pack2(a.y); wp[2]  = pack2(a.z); wp[3]  = pack2(a.w);
        wp[4]  = pack2(b.x); wp[5]  = pack2(b.y); wp[6]  = pack2(b.z); wp[7]  = pack2(b.w);
        wp[8]  = pack2(c.x); wp[9]  = pack2(c.y); wp[10] = pack2(c.z); wp[11] = pack2(c.w);
        wp[12] = pack2(d.x); wp[13] = pack2(d.y); wp[14] = pack2(d.z); wp[15] = pack2(d.w);
    }

    int q = jg;                        // q = jg + Gl; e-group = [8q, 8q+8)
    for (int Gl = 0; Gl < NGRP; ++Gl, ++q) {
        // K loads: cells at u64 base 8q, 16B units permuted by m3 = (q>>1)&3
        const int m3 = (q >> 1) & 3;
        const u64* a = krow0 + 8 * q;
        const u64* b = krow1 + 8 * q;
        const int o0 = 2 * (0 ^ m3), o1 = 2 * (1 ^ m3);
        const int o2 = 2 * (2 ^ m3), o3 = 2 * (3 ^ m3);
        u64 kk0[8], kk1[8];
        {
            ulonglong2 v;
            v = *(const ulonglong2*)(a + o0); kk0[0] = v.x; kk0[1] = v.y;
            v = *(const ulonglong2*)(a + o1); kk0[2] = v.x; kk0[3] = v.y;
            v = *(const ulonglong2*)(a + o2); kk0[4] = v.x; kk0[5] = v.y;
            v = *(const ulonglong2*)(a + o3); kk0[6] = v.x; kk0[7] = v.y;
            v = *(const ulonglong2*)(b + o0); kk1[0] = v.x; kk1[1] = v.y;
            v = *(const ulonglong2*)(b + o1); kk1[2] = v.x; kk1[3] = v.y;
            v = *(const ulonglong2*)(b + o2); kk1[4] = v.x; kk1[5] = v.y;
            v = *(const ulonglong2*)(b + o3); kk1[6] = v.x; kk1[7] = v.y;
        }
        // 128 packed FMAs: acc[pg][jj] += K2[pg][t] * img2[7 - t + jj]
#pragma unroll
        for (int t = 0; t < 8; t++) {
#pragma unroll
            for (int jj = 0; jj < 8; jj++) {
                acc0[jj] = ffma2(kk0[t], wp[7 - t + jj], acc0[jj]);
                acc1[jj] = ffma2(kk1[t], wp[7 - t + jj], acc1[jj]);
            }
        }
        // slide broadcast window down by 8
        if (Gl < NGRP - 1) {
#pragma unroll
            for (int k = 15; k >= 8; k--) wp[k] = wp[k - 8];
            const float4* p = (const float4*)(simg + 752 - 8 * Gl);
            float4 va = p[0], vb = p[1];
            wp[0] = pack2(va.x); wp[1] = pack2(va.y); wp[2] = pack2(va.z); wp[3] = pack2(va.w);
            wp[4] = pack2(vb.x); wp[5] = pack2(vb.y); wp[6] = pack2(vb.z); wp[7] = pack2(vb.w);
        }
    }

    // ---- write partials: acc0 -> rows 4ig,4ig+1 ; acc1 -> rows 4ig+2,4ig+3
    float* dst = g_part + ii * (OUT_H * OUT_W);
    const int i0 = 4 * ig;
    float lo[8], hi[8];
#pragma unroll
    for (int jj = 0; jj < 8; jj++) unpack2(acc0[jj], lo[jj], hi[jj]);
    {
        float4* qa = (float4*)(dst + (i0 + 0) * OUT_W + 8 * jg);
        float4* qb = (float4*)(dst + (i0 + 1) * OUT_W + 8 * jg);
        qa[0] = make_float4(lo[0], lo[1], lo[2], lo[3]);
        qa[1] = make_float4(lo[4], lo[5], lo[6], lo[7]);
        qb[0] = make_float4(hi[0], hi[1], hi[2], hi[3]);
        qb[1] = make_float4(hi[4], hi[5], hi[6], hi[7]);
    }
#pragma unroll
    for (int jj = 0; jj < 8; jj++) unpack2(acc1[jj], lo[jj], hi[jj]);
    {
        float4* qa = (float4*)(dst + (i0 + 2) * OUT_W + 8 * jg);
        float4* qb = (float4*)(dst + (i0 + 3) * OUT_W + 8 * jg);
        qa[0] = make_float4(lo[0], lo[1], lo[2], lo[3]);
        qa[1] = make_float4(lo[4], lo[5], lo[6], lo[7]);
        qb[0] = make_float4(hi[0], hi[1], hi[2], hi[3]);
        qb[1] = make_float4(hi[4], hi[5], hi[6], hi[7]);
    }
}

// ---------------------------------------------------------------------------
// Kernel 3: sum the 256 partials per output element (deterministic).
// ---------------------------------------------------------------------------
__global__ void reduce_kernel(float* __restrict__ out) {
    int o = blockIdx.x * blockDim.x + threadIdx.x;   // 0..8191
    float s0 = 0.f, s1 = 0.f, s2 = 0.f, s3 = 0.f;
#pragma unroll 4
    for (int c = 0; c < NBLK; c += 4) {
        s0 += g_part[(c + 0) * (OUT_H * OUT_W) + o];
        s1 += g_part[(c + 1) * (OUT_H * OUT_W) + o];
        s2 += g_part[(c + 2) * (OUT_H * OUT_W) + o];
        s3 += g_part[(c + 3) * (OUT_H * OUT_W) + o];
    }
    out[o] = (s0 + s1) + (s2 + s3);
}

// ---------------------------------------------------------------------------
extern "C" void kernel_launch(void* const* d_in, const int* in_sizes, int n_in,
                              void* d_out, int out_size) {
    const float* img = (const float*)d_in[0];   // [256, 512] f32
    const float* pos = (const float*)d_in[1];   // [2] f32
    float* out = (float*)d_out;                 // [32, 256] f32

    cudaFuncSetAttribute(conv_part_kernel,
                         cudaFuncAttributeMaxDynamicSharedMemorySize, SMEM_BYTES);
    fill_k_kernel<<<D_SIZE, 256>>>(pos);
    conv_part_kernel<<<NBLK, 256, SMEM_BYTES>>>(img);
    reduce_kernel<<<(OUT_H * OUT_W) / 256, 256>>>(out);
}

// round 5
// speedup vs baseline: 2.4390x; 2.4390x over previous
#include <cuda_runtime.h>

#define OUT_H    32
#define OUT_W    256
#define IMG_W    512
#define NBLK     128            // 2 image rows (ii) per block
#define SK_T     33             // staged K d-rows per block (2 ii share 31)
#define SK_E     776            // e dim padded to 97*8 (real e < 767, rest 0)
#define SIMG_LEN 1032           // padded image row: data at [264, 776)
#define SK_ELEMS (SK_T * SK_E)                     // 25608
#define SMEM_FLOATS (SK_ELEMS + 2 * SIMG_LEN)      // 27672
#define SMEM_BYTES  (SMEM_FLOATS * 4)              // 110688 B -> occ 1

__device__ float g_part[NBLK * OUT_H * OUT_W];     // 4 MB partials

__device__ __forceinline__ float frcp(float x) {
    float r; asm("rcp.approx.f32 %0, %1;" : "=f"(r) : "f"(x)); return r;
}
__device__ __forceinline__ float tf32r(float x) {
    float r; asm("cvt.rna.tf32.f32 %0, %1;" : "=f"(r) : "f"(x)); return r;
}
// m16n8k8 tf32 MMA: D(16x8 f32) += A(16x8 row) * B(8x8 col)
__device__ __forceinline__ void mma_tf32(float* d, const unsigned* a, const unsigned* b) {
    asm volatile(
        "mma.sync.aligned.m16n8k8.row.col.f32.tf32.tf32.f32 "
        "{%0,%1,%2,%3}, {%4,%5,%6,%7}, {%8,%9}, {%0,%1,%2,%3};"
        : "+f"(d[0]), "+f"(d[1]), "+f"(d[2]), "+f"(d[3])
        : "r"(a[0]), "r"(a[1]), "r"(a[2]), "r"(a[3]), "r"(b[0]), "r"(b[1]));
}

// ---------------------------------------------------------------------------
// One block per ii-pair {ii0, ii0+1}. Computes
//   part[blk][i][j] = sum_{s,e} K[i-(ii0+s)+255, e] * simg_s[j + 775 - e]
// as tf32 tensor-core GEMMs: M=j(256), N=i(32), K=e(776), accumulated over s.
// A operand (Toeplitz of image row) read directly from SMEM per fragment —
// never materialized. B = 33 staged K rows (built in-SMEM with MUFU.RCP).
// ---------------------------------------------------------------------------
__global__ void __launch_bounds__(256, 1)
conv_mma_kernel(const float* __restrict__ img, const float* __restrict__ pos) {
    extern __shared__ float smem[];
    float* sk   = smem;                 // [SK_T][SK_E], t-major
    float* simg = smem + SK_ELEMS;      // [2][SIMG_LEN]

    const int   ii0 = blockIdx.x * 2;
    const int   tid = threadIdx.x;
    const float p0 = pos[0], p1 = pos[1];

    // ---- stage 2 image rows (tf32-rounded, zero-padded) ----
    for (int x = tid; x < 2 * SIMG_LEN; x += 256) {
        int s  = (x >= SIMG_LEN) ? 1 : 0;
        int xi = x - s * SIMG_LEN;
        float v = 0.0f;
        if (xi >= 264 && xi < 776) v = img[(ii0 + s) * IMG_W + (xi - 264)];
        simg[x] = tf32r(v);
    }
    // ---- build K slice in SMEM: row t holds d = (254 - ii0) + t ----
    //   K = 1/((t - 1 - ii0 + p0)^2 + (e - 511 + p1)^2), e<767; else 0
    for (int t = 0; t < SK_T; t++) {
        float dx  = (float)(t - 1 - ii0) + p0;
        float dx2 = dx * dx;
        for (int e = tid; e < SK_E; e += 256) {
            float v = 0.0f;
            if (e < 767) {
                float dy = (float)(e - 511) + p1;
                v = frcp(fmaf(dy, dy, dx2));
            }
            sk[t * SK_E + e] = tf32r(v);
        }
    }
    __syncthreads();

    // ---- main loop: warp w owns j in [32w, 32w+32) (2 m-tiles), all 4 n-tiles
    const int w    = tid >> 5;
    const int lane = tid & 31;
    const int r    = lane >> 2;     // fragment row group
    const int c    = lane & 3;      // fragment col group
    const int jbase = 32 * w;
    const int q_lo  = 4 * w;        // k-steps q in [4w, 4w+68): e covers [32w, 32w+543]

    float acc[2][4][4];
#pragma unroll
    for (int m = 0; m < 2; m++)
#pragma unroll
        for (int n = 0; n < 4; n++)
#pragma unroll
            for (int k = 0; k < 4; k++) acc[m][n][k] = 0.0f;

#pragma unroll 1
    for (int s = 0; s < 2; s++) {
        // A: simg[s][ jbase + 16m + row + 775 - (e0 + col) ], row=r(+8), col=c(+4)
        const float* pA = simg + s * SIMG_LEN + jbase + 775 + r - c;
        // B: sk[ (8n + r + 1 - s) ][ e0 + c (+4) ]
        const float* pB = sk + (r + 1 - s) * SK_E + c;

        for (int qq = 0; qq < 68; qq++) {
            const int e0 = 8 * (q_lo + qq);
            unsigned a[2][4], b[4][2];
#pragma unroll
            for (int m = 0; m < 2; m++) {
                const float* pa = pA + 16 * m - e0;
                a[m][0] = __float_as_uint(pa[0]);    // (r,   c)
                a[m][1] = __float_as_uint(pa[8]);    // (r+8, c)
                a[m][2] = __float_as_uint(pa[-4]);   // (r,   c+4)
                a[m][3] = __float_as_uint(pa[4]);    // (r+8, c+4)
            }
#pragma unroll
            for (int n = 0; n < 4; n++) {
                const float* pb = pB + n * (8 * SK_E) + e0;
                b[n][0] = __float_as_uint(pb[0]);    // (k=c,   n=r)
                b[n][1] = __float_as_uint(pb[4]);    // (k=c+4, n=r)
            }
#pragma unroll
            for (int m = 0; m < 2; m++)
#pragma unroll
                for (int n = 0; n < 4; n++)
                    mma_tf32(acc[m][n], a[m], b[n]);
        }
    }

    // ---- write partials: D frag (row=j, col=i): d0:(j0,i0) d1:(j0,i0+1)
    //      d2:(j0+8,i0) d3:(j0+8,i0+1)
    float* dst = g_part + blockIdx.x * (OUT_H * OUT_W);
#pragma unroll
    for (int m = 0; m < 2; m++) {
        const int j0 = jbase + 16 * m + r;
#pragma unroll
        for (int n = 0; n < 4; n++) {
            const int i0 = 8 * n + 2 * c;
            dst[(i0    ) * OUT_W + j0    ] = acc[m][n][0];
            dst[(i0 + 1) * OUT_W + j0    ] = acc[m][n][1];
            dst[(i0    ) * OUT_W + j0 + 8] = acc[m][n][2];
            dst[(i0 + 1) * OUT_W + j0 + 8] = acc[m][n][3];
        }
    }
}

// ---------------------------------------------------------------------------
// Sum the 128 partials per output element (deterministic order).
// ---------------------------------------------------------------------------
__global__ void reduce_kernel(float* __restrict__ out) {
    int o = blockIdx.x * blockDim.x + threadIdx.x;   // 0..8191
    float s0 = 0.f, s1 = 0.f, s2 = 0.f, s3 = 0.f;
#pragma unroll 4
    for (int c = 0; c < NBLK; c += 4) {
        s0 += g_part[(c + 0) * (OUT_H * OUT_W) + o];
        s1 += g_part[(c + 1) * (OUT_H * OUT_W) + o];
        s2 += g_part[(c + 2) * (OUT_H * OUT_W) + o];
        s3 += g_part[(c + 3) * (OUT_H * OUT_W) + o];
    }
    out[o] = (s0 + s1) + (s2 + s3);
}

// ---------------------------------------------------------------------------
extern "C" void kernel_launch(void* const* d_in, const int* in_sizes, int n_in,
                              void* d_out, int out_size) {
    const float* img = (const float*)d_in[0];   // [256, 512] f32
    const float* pos = (const float*)d_in[1];   // [2] f32
    float* out = (float*)d_out;                 // [32, 256] f32

    cudaFuncSetAttribute(conv_mma_kernel,
                         cudaFuncAttributeMaxDynamicSharedMemorySize, SMEM_BYTES);
    conv_mma_kernel<<<NBLK, 256, SMEM_BYTES>>>(img, pos);
    reduce_kernel<<<(OUT_H * OUT_W) / 256, 256>>>(out);
}

// round 6
// speedup vs baseline: 4.3473x; 1.7824x over previous
#include <cuda_runtime.h>
#include <cuda_bf16.h>

#define OUT_W    256
#define IMG_W    512
#define NPAIR    128
#define NBLK     256            // (ii-pair p) x (i-half h)
#define SK_T     17             // K rows per block
#define SK_E     776            // bf16 per K row; stride 1552B = 16 mod 128 -> conflict-free
#define SK_W     388            // u32 words per K row
#define SREV_LEN 1032
#define OFF_K    0
#define OFF_SREV 26400          // 17*776*2 = 26392, padded
#define OFF_SREVB 30528         // + 2*1032*2
#define SMEM_BYTES 34656

__device__ float g_part[NPAIR * 32 * OUT_W];    // 4 MB partials [p][i][j]
__device__ float g_red[8 * 32 * OUT_W];         // 256 KB stage-A output

__device__ __forceinline__ float frcp(float x) {
    float r; asm("rcp.approx.f32 %0, %1;" : "=f"(r) : "f"(x)); return r;
}
// D(16x8 f32) += A(16x16 bf16 row) * B(16x8 bf16 col)
__device__ __forceinline__ void mma_bf16(float* d, const unsigned* a, const unsigned* b) {
    asm volatile(
        "mma.sync.aligned.m16n8k16.row.col.f32.bf16.bf16.f32 "
        "{%0,%1,%2,%3}, {%4,%5,%6,%7}, {%8,%9}, {%0,%1,%2,%3};"
        : "+f"(d[0]), "+f"(d[1]), "+f"(d[2]), "+f"(d[3])
        : "r"(a[0]), "r"(a[1]), "r"(a[2]), "r"(a[3]), "r"(b[0]), "r"(b[1]));
}

// ---------------------------------------------------------------------------
// Block (p, h): ii in {2p, 2p+1}, i in [16h, 16h+16).
//   part[p][i][j] = sum_{s,e} K[i-(2p+s)+255, e] * img_s_rev stuff
// GEMM: M=j(256), N=i(16), K=e(544-span per warp), bf16 MMA, fp32 accum.
// A operand is the reversed image row read in place (Toeplitz, never
// materialized); a3 == a0 by Toeplitz identity. B = 17 staged K rows.
// ---------------------------------------------------------------------------
__global__ void __launch_bounds__(256)
conv_mma_kernel(const float* __restrict__ img, const float* __restrict__ pos) {
    extern __shared__ char smem[];
    __nv_bfloat16* sr  = (__nv_bfloat16*)(smem + OFF_SREV);   // [2][1032] reversed img
    __nv_bfloat16* srB = (__nv_bfloat16*)(smem + OFF_SREVB);  // shifted copy (+1)
    unsigned*      skw = (unsigned*)(smem + OFF_K);           // K rows as bf16x2 words

    const int bx = blockIdx.x;
    const int p  = bx >> 1, h = bx & 1;
    const int tid = threadIdx.x;
    const float p0 = pos[0], p1 = pos[1];

    // ---- reversed image rows, bf16: sr[s][z] = (256<=z<=767) ? img[2p+s][767-z] : 0
    for (int x = tid; x < 2 * SREV_LEN; x += 256) {
        int s = (x >= SREV_LEN) ? 1 : 0;
        int z = x - s * SREV_LEN;
        float v0 = (z >= 256 && z <= 767) ? img[(2 * p + s) * IMG_W + (767 - z)] : 0.f;
        int z1 = z + 1;
        float v1 = (z1 >= 256 && z1 <= 767) ? img[(2 * p + s) * IMG_W + (767 - z1)] : 0.f;
        sr [x] = __float2bfloat16_rn(v0);
        srB[x] = __float2bfloat16_rn(v1);
    }
    // ---- K rows: row t holds d-255 = 16h - 2p - 1 + t
    for (int t = 0; t < SK_T; t++) {
        float dx  = (float)(16 * h - 2 * p - 1 + t) + p0;
        float dx2 = dx * dx;
        for (int u = tid; u < SK_W; u += 256) {
            float dy0 = (float)(2 * u - 511) + p1;
            float dy1 = dy0 + 1.0f;
            float v0 = frcp(fmaf(dy0, dy0, dx2));
            float v1 = frcp(fmaf(dy1, dy1, dx2));
            unsigned wv;
            asm("cvt.rn.bf16x2.f32 %0, %1, %2;" : "=r"(wv) : "f"(v1), "f"(v0));
            skw[t * SK_W + u] = wv;
        }
    }
    __syncthreads();

    // ---- main loop: warp w owns j in [32w, 32w+32), 2 m-tiles x 2 n-tiles
    const int w    = tid >> 5;
    const int lane = tid & 31;
    const int r    = lane >> 2;
    const int c    = lane & 3;
    const int jbase = 32 * w;
    const int sel   = r & 1;        // j-parity -> which shifted image copy

    float acc[2][2][4];
#pragma unroll
    for (int m = 0; m < 2; m++)
#pragma unroll
        for (int n = 0; n < 2; n++)
#pragma unroll
            for (int k = 0; k < 4; k++) acc[m][n][k] = 0.f;

#pragma unroll 1
    for (int s = 0; s < 2; s++) {
        const unsigned* As = (const unsigned*)(sel ? (srB + s * SREV_LEN)
                                                   : (sr  + s * SREV_LEN));
        const int tB0 = r + 1 - s;             // K row for n-tile 0
        // A word base (e0=0, m=0): y = 2c - (jbase + r) + 256; word=(y-sel)/2
        const int aw0 = (2 * c - jbase - r + 256 - sel) >> 1;

        for (int q = 0; q < 34; q++) {
            const int e0 = 32 * w + 16 * q;
            const int ew = e0 >> 1;
            unsigned a[2][4], b[2][2];
#pragma unroll
            for (int m = 0; m < 2; m++) {
                int w0 = aw0 + ew - 8 * m;     // -16 j-elements = -8 words
                unsigned v0 = As[w0];
                a[m][0] = v0;                  // (r,   2c:2c+1)
                a[m][1] = As[w0 - 4];          // (r+8, 2c:2c+1)
                a[m][2] = As[w0 + 4];          // (r,   2c+8:2c+9)
                a[m][3] = v0;                  // (r+8, 2c+8) == a0 (Toeplitz)
            }
#pragma unroll
            for (int nn = 0; nn < 2; nn++) {
                int wb = (8 * nn + tB0) * SK_W + ew + c;
                b[nn][0] = skw[wb];            // (2c:2c+1,  r)
                b[nn][1] = skw[wb + 4];        // (2c+8:+9,  r)
            }
#pragma unroll
            for (int m = 0; m < 2; m++)
#pragma unroll
                for (int nn = 0; nn < 2; nn++)
                    mma_bf16(acc[m][nn], a[m], b[nn]);
        }
    }

    // ---- write partials: [p][i][j], this block covers i in [16h,16h+16)
    float* dst = g_part + p * (32 * OUT_W) + (16 * h) * OUT_W;
#pragma unroll
    for (int m = 0; m < 2; m++) {
        const int j0 = jbase + 16 * m + r;
#pragma unroll
        for (int nn = 0; nn < 2; nn++) {
            const int irow = 8 * nn + 2 * c;
            dst[(irow    ) * OUT_W + j0    ] = acc[m][nn][0];
            dst[(irow + 1) * OUT_W + j0    ] = acc[m][nn][1];
            dst[(irow    ) * OUT_W + j0 + 8] = acc[m][nn][2];
            dst[(irow + 1) * OUT_W + j0 + 8] = acc[m][nn][3];
        }
    }
}

// ---------------------------------------------------------------------------
// Two-stage deterministic reduction over the 128 ii-pair chunks.
// ---------------------------------------------------------------------------
__global__ void reduce_a_kernel() {
    const int g   = blockIdx.x >> 5;                 // 8 chunk-groups
    const int o   = (blockIdx.x & 31) * 256 + threadIdx.x;
    const int c0  = g * 16;
    float s0 = 0.f, s1 = 0.f, s2 = 0.f, s3 = 0.f;
#pragma unroll
    for (int c = 0; c < 16; c += 4) {
        s0 += g_part[(c0 + c + 0) * 8192 + o];
        s1 += g_part[(c0 + c + 1) * 8192 + o];
        s2 += g_part[(c0 + c + 2) * 8192 + o];
        s3 += g_part[(c0 + c + 3) * 8192 + o];
    }
    g_red[g * 8192 + o] = (s0 + s1) + (s2 + s3);
}

__global__ void reduce_b_kernel(float* __restrict__ out) {
    const int o = blockIdx.x * 256 + threadIdx.x;
    float s = 0.f;
#pragma unroll
    for (int g = 0; g < 8; g++) s += g_red[g * 8192 + o];
    out[o] = s;
}

// ---------------------------------------------------------------------------
extern "C" void kernel_launch(void* const* d_in, const int* in_sizes, int n_in,
                              void* d_out, int out_size) {
    const float* img = (const float*)d_in[0];   // [256, 512] f32
    const float* pos = (const float*)d_in[1];   // [2] f32
    float* out = (float*)d_out;                 // [32, 256] f32

    cudaFuncSetAttribute(conv_mma_kernel,
                         cudaFuncAttributeMaxDynamicSharedMemorySize, SMEM_BYTES);
    conv_mma_kernel<<<NBLK, 256, SMEM_BYTES>>>(img, pos);
    reduce_a_kernel<<<256, 256>>>();
    reduce_b_kernel<<<32, 256>>>(out);
}